// round 8
// baseline (speedup 1.0000x reference)
#include <cuda_runtime.h>
#include <cstdint>

#define M_NODES 150000      // 3 * NATOMS
#define NE_EDGES 1500000
#define NE_HALF  750000
#define NHEADS 4
#define DHEAD 16

typedef unsigned long long ull;

// Device-global scratch
__device__ float g_t4[M_NODES * 4];       // per-node low-rank features
__device__ float g_UZ[M_NODES * 20];      // [4 heads x 4 U] + [4 Z]
__device__ float g_A[256];                // A[d*4+i] = (W2@W)[i,d]
__device__ float g_c[64];                 // c[d] = (b2@W + b)[d]
// dup-packed weight tables for the edge kernel (each f32 duplicated in both lanes)
__device__ ull   g_Wd[64 * 16];           // [d][k] = dup(W[k,d])
__device__ ull   g_Ad[64 * 4];            // [d][i] = dup(A[i,d])
__device__ ull   g_BCd[64 * 2];           // [d][0] = dup(b[d]), [d][1] = dup(c[d])
__device__ int   g_idx_is_64;

__device__ __forceinline__ float elu1(float v) {
    return v > 0.0f ? v : (__expf(v) - 1.0f);
}

__device__ __forceinline__ void red_add_v4(float* addr, float4 v) {
    asm volatile("red.global.add.v4.f32 [%0], {%1, %2, %3, %4};"
                 :: "l"(addr), "f"(v.x), "f"(v.y), "f"(v.z), "f"(v.w)
                 : "memory");
}

// packed f32x2 helpers (Blackwell): FFMA2 via PTX only
__device__ __forceinline__ ull pk2(float lo, float hi) {
    ull r; asm("mov.b64 %0, {%1, %2};" : "=l"(r) : "f"(lo), "f"(hi)); return r;
}
__device__ __forceinline__ void upk2(float& lo, float& hi, ull v) {
    asm("mov.b64 {%0, %1}, %2;" : "=f"(lo), "=f"(hi) : "l"(v));
}
__device__ __forceinline__ void fma2(ull& d, ull a, ull b) {   // d = a*b + d
    asm("fma.rn.f32x2 %0, %1, %2, %0;" : "+l"(d) : "l"(a), "l"(b));
}
__device__ __forceinline__ ull mul2(ull a, ull b) {
    ull r; asm("mul.rn.f32x2 %0, %1, %2;" : "=l"(r) : "l"(a), "l"(b)); return r;
}
__device__ __forceinline__ ull dupf(float v) {
    uint32_t b = __float_as_uint(v);
    return (ull)b | ((ull)b << 32);
}

// ---------------------------------------------------------------------------
__global__ void probe_idx_kernel(const int* __restrict__ ei32) {
    int z = (ei32[1] == 0) & (ei32[3] == 0) & (ei32[5] == 0) & (ei32[7] == 0);
    g_idx_is_64 = z;
}

// ---------------------------------------------------------------------------
// Setup: A = W2@W, c = b2@W + b; dup-packed tables for edge kernel.
// ---------------------------------------------------------------------------
__global__ void setup_kernel(const float* __restrict__ W2, const float* __restrict__ b2,
                             const float* __restrict__ W,  const float* __restrict__ b) {
    __shared__ float shA[256], shc[64];
    int t = threadIdx.x;           // t = d*4 + i
    int d = t >> 2, i = t & 3;
    float a = 0.f;
#pragma unroll
    for (int k = 0; k < 16; k++) a = fmaf(W2[i * 16 + k], W[k * 64 + d], a);
    shA[t] = a;
    if (i == 0) {
        float cc = b[d];
#pragma unroll
        for (int k = 0; k < 16; k++) cc = fmaf(b2[k], W[k * 64 + d], cc);
        shc[d] = cc;
    }
    __syncthreads();

    g_A[t] = shA[t];
    if (t < 64) g_c[t] = shc[t];

    if (t < 64) {                  // d = t
        int dd = t;
        g_BCd[2 * dd]     = dupf(b[dd]);
        g_BCd[2 * dd + 1] = dupf(shc[dd]);
#pragma unroll
        for (int i2 = 0; i2 < 4; i2++)
            g_Ad[dd * 4 + i2] = dupf(shA[dd * 4 + i2]);
#pragma unroll
        for (int k = 0; k < 16; k++)
            g_Wd[dd * 16 + k] = dupf(W[k * 64 + dd]);
    }
}

// ---------------------------------------------------------------------------
// Kernel A: t4[m] = elu(x*W1 + b1); zero the UZ accumulator row.
// ---------------------------------------------------------------------------
__global__ __launch_bounds__(256)
void t4_kernel(const float* __restrict__ ev,
               const float* __restrict__ W1, const float* __restrict__ b1) {
    __shared__ float sW1[4], sb1[4];
    int t = threadIdx.x;
    if (t < 4) { sW1[t] = W1[t]; sb1[t] = b1[t]; }
    __syncthreads();

    int m = blockIdx.x * blockDim.x + t;
    if (m >= M_NODES) return;

    float x = ev[m];
    float4 t4;
    t4.x = elu1(fmaf(x, sW1[0], sb1[0]));
    t4.y = elu1(fmaf(x, sW1[1], sb1[1]));
    t4.z = elu1(fmaf(x, sW1[2], sb1[2]));
    t4.w = elu1(fmaf(x, sW1[3], sb1[3]));
    reinterpret_cast<float4*>(g_t4)[m] = t4;

    float4 z4 = make_float4(0.f, 0.f, 0.f, 0.f);
    float4* uz = reinterpret_cast<float4*>(g_UZ + (size_t)m * 20);
#pragma unroll
    for (int k = 0; k < 5; k++) uz[k] = z4;
}

// ---------------------------------------------------------------------------
// Kernel B: TWO edges per thread, packed as (edgeA, edgeB) in the two f32x2
// lanes. Weights dup-packed per single d. Halves register state vs R7.
// ---------------------------------------------------------------------------
__global__ __launch_bounds__(128, 5)
void edge_kernel(const void* __restrict__ ei_raw,
                 const float* __restrict__ ef,
                 const float* __restrict__ W2, const float* __restrict__ b2) {
    __shared__ ull   sWd[1024];        // [d][k] dup pairs (8 KB)
    __shared__ ull   sAd[256];         // [d][i] dup pairs (2 KB)
    __shared__ ull   sBC[128];         // [d][{b,c}] dup pairs (1 KB)
    __shared__ float4 sW2[16];         // (W2[0,k],W2[1,k],W2[2,k],W2[3,k])
    __shared__ float  sb2[16];

    int t = threadIdx.x;
#pragma unroll
    for (int i = 0; i < 8; i++) sWd[t + 128 * i] = g_Wd[t + 128 * i];
    sAd[t] = g_Ad[t]; sAd[t + 128] = g_Ad[t + 128];
    if (t < 128) sBC[t] = g_BCd[t];
    if (t < 16) {
        sW2[t] = make_float4(W2[t], W2[16 + t], W2[32 + t], W2[48 + t]);
        sb2[t] = b2[t];
    }
    __syncthreads();

    int ea = blockIdx.x * blockDim.x + t;
    if (ea >= NE_HALF) return;
    int eb = ea + NE_HALF;

    int srcA, dstA, srcB, dstB;
    if (g_idx_is_64) {
        const long long* ei = (const long long*)ei_raw;
        srcA = (int)__ldg(ei + ea);
        dstA = (int)__ldg(ei + NE_EDGES + ea);
        srcB = (int)__ldg(ei + eb);
        dstB = (int)__ldg(ei + NE_EDGES + eb);
    } else {
        const int* ei = (const int*)ei_raw;
        srcA = __ldg(ei + ea);
        dstA = __ldg(ei + NE_EDGES + ea);
        srcB = __ldg(ei + eb);
        dstB = __ldg(ei + NE_EDGES + eb);
    }

    // front-batch all gathers (MLP)
    float4 tsvA = __ldg(reinterpret_cast<const float4*>(g_t4) + srcA);
    float4 tqvA = __ldg(reinterpret_cast<const float4*>(g_t4) + dstA);
    float4 tsvB = __ldg(reinterpret_cast<const float4*>(g_t4) + srcB);
    float4 tqvB = __ldg(reinterpret_cast<const float4*>(g_t4) + dstB);
    float4 fA = __ldg(reinterpret_cast<const float4*>(ef) + ea);
    float4 fB = __ldg(reinterpret_cast<const float4*>(ef) + eb);

    // e16 for both edges, packed (A,B) per k
    ull e2[16];
#pragma unroll
    for (int k = 0; k < 16; k++) {
        float4 w = sW2[k];
        float bb = sb2[k];
        float va = bb, vb = bb;
        va = fmaf(fA.x, w.x, va); vb = fmaf(fB.x, w.x, vb);
        va = fmaf(fA.y, w.y, va); vb = fmaf(fB.y, w.y, vb);
        va = fmaf(fA.z, w.z, va); vb = fmaf(fB.z, w.z, vb);
        va = fmaf(fA.w, w.w, va); vb = fmaf(fB.w, w.w, vb);
        e2[k] = pk2(elu1(va), elu1(vb));
    }

    ull tq2[4] = {pk2(tqvA.x, tqvB.x), pk2(tqvA.y, tqvB.y),
                  pk2(tqvA.z, tqvB.z), pk2(tqvA.w, tqvB.w)};
    float tsA[4] = {tsvA.x, tsvA.y, tsvA.z, tsvA.w};
    float tsB[4] = {tsvB.x, tsvB.y, tsvB.z, tsvB.w};

    float* uzA = g_UZ + (size_t)dstA * 20;
    float* uzB = g_UZ + (size_t)dstB * 20;
    float zaccA[NHEADS], zaccB[NHEADS];

#pragma unroll
    for (int h = 0; h < NHEADS; h++) {
        ull V0 = 0, V1 = 0, V2 = 0, V3 = 0, Vc = 0;
#pragma unroll
        for (int dd = 0; dd < 16; dd++) {
            int d = h * 16 + dd;
            ulonglong2 bc = reinterpret_cast<const ulonglong2*>(sBC)[d];
            ull E2 = bc.x;
            const ulonglong2* wp = reinterpret_cast<const ulonglong2*>(sWd + d * 16);
#pragma unroll
            for (int kk = 0; kk < 8; kk++) {
                ulonglong2 ww = wp[kk];
                fma2(E2, e2[2 * kk],     ww.x);
                fma2(E2, e2[2 * kk + 1], ww.y);
            }
            ulonglong2 a01 = reinterpret_cast<const ulonglong2*>(sAd)[d * 2];
            ulonglong2 a23 = reinterpret_cast<const ulonglong2*>(sAd)[d * 2 + 1];
            ull Q2 = bc.y;
            fma2(Q2, tq2[0], a01.x); fma2(Q2, tq2[1], a01.y);
            fma2(Q2, tq2[2], a23.x); fma2(Q2, tq2[3], a23.y);

            ull R2 = mul2(E2, Q2);
            fma2(V0, R2, a01.x); fma2(V1, R2, a01.y);
            fma2(V2, R2, a23.x); fma2(V3, R2, a23.y);
            fma2(Vc, R2, bc.y);
        }
        // lanes ARE the edges: direct unpack, no cross-lane add
        float v0a, v0b, v1a, v1b, v2a, v2b, v3a, v3b, vca, vcb;
        upk2(v0a, v0b, V0); upk2(v1a, v1b, V1);
        upk2(v2a, v2b, V2); upk2(v3a, v3b, V3);
        upk2(vca, vcb, Vc);

        float scA = vca;
        scA = fmaf(tsA[0], v0a, scA); scA = fmaf(tsA[1], v1a, scA);
        scA = fmaf(tsA[2], v2a, scA); scA = fmaf(tsA[3], v3a, scA);
        scA *= 0.25f;
        scA = fminf(fmaxf(scA, -5.0f), 5.0f);
        float wA = __expf(scA);
        zaccA[h] = wA;
        red_add_v4(uzA + h * 4, make_float4(tsA[0] * wA, tsA[1] * wA,
                                            tsA[2] * wA, tsA[3] * wA));

        float scB = vcb;
        scB = fmaf(tsB[0], v0b, scB); scB = fmaf(tsB[1], v1b, scB);
        scB = fmaf(tsB[2], v2b, scB); scB = fmaf(tsB[3], v3b, scB);
        scB *= 0.25f;
        scB = fminf(fmaxf(scB, -5.0f), 5.0f);
        float wB = __expf(scB);
        zaccB[h] = wB;
        red_add_v4(uzB + h * 4, make_float4(tsB[0] * wB, tsB[1] * wB,
                                            tsB[2] * wB, tsB[3] * wB));
    }
    red_add_v4(uzA + 16, make_float4(zaccA[0], zaccA[1], zaccA[2], zaccA[3]));
    red_add_v4(uzB + 16, make_float4(zaccB[0], zaccB[1], zaccB[2], zaccB[3]));
}

// ---------------------------------------------------------------------------
// Kernel C: wV_d = A[:,d].U_h + c_d*Z_h ; h_d = wV_d/(Z_h+1e-6);
//           out = elu(h @ Wout + bout) @ Wout1 + bout1
// ---------------------------------------------------------------------------
__global__ __launch_bounds__(256)
void out_kernel(float* __restrict__ out,
                const float* __restrict__ Wout,  const float* __restrict__ bout,
                const float* __restrict__ Wout1, const float* __restrict__ bout1) {
    __shared__ float sWo[1024], sbo[16], sW1[16], sb1, sA[256], sc_[64];
    int t = threadIdx.x;
    for (int i = t; i < 1024; i += blockDim.x) sWo[i] = Wout[i];
    if (t < 16) { sbo[t] = bout[t]; sW1[t] = Wout1[t]; }
    if (t == 0) sb1 = bout1[0];
    if (t < 256) sA[t] = g_A[t];
    if (t < 64)  sc_[t] = g_c[t];
    __syncthreads();

    int m = blockIdx.x * blockDim.x + t;
    if (m >= M_NODES) return;

    const float4* uz4 = reinterpret_cast<const float4*>(g_UZ + (size_t)m * 20);
    float4 U0 = uz4[0], U1 = uz4[1], U2 = uz4[2], U3 = uz4[3], Zv = uz4[4];
    float U[NHEADS][4] = {
        {U0.x, U0.y, U0.z, U0.w}, {U1.x, U1.y, U1.z, U1.w},
        {U2.x, U2.y, U2.z, U2.w}, {U3.x, U3.y, U3.z, U3.w}};
    float Z[NHEADS] = {Zv.x, Zv.y, Zv.z, Zv.w};

    float acc[16];
#pragma unroll
    for (int k = 0; k < 16; k++) acc[k] = sbo[k];

#pragma unroll
    for (int h = 0; h < NHEADS; h++) {
        float rz = 1.0f / (Z[h] + 1e-6f);
#pragma unroll
        for (int dd = 0; dd < 16; dd++) {
            int d = h * 16 + dd;
            float wv = sc_[d] * Z[h];
#pragma unroll
            for (int i = 0; i < 4; i++) wv = fmaf(sA[d * 4 + i], U[h][i], wv);
            float hv = wv * rz;
#pragma unroll
            for (int k = 0; k < 16; k++) acc[k] = fmaf(hv, sWo[d * 16 + k], acc[k]);
        }
    }

    float val = sb1;
#pragma unroll
    for (int k = 0; k < 16; k++) {
        float a = elu1(acc[k]);
        val = fmaf(a, sW1[k], val);
    }
    out[m] = val;
}

// ---------------------------------------------------------------------------
extern "C" void kernel_launch(void* const* d_in, const int* in_sizes, int n_in,
                              void* d_out, int out_size) {
    // order: node_attr, edge_index, edge_feature, edge_vector,
    //        W1, b1, W2, b2, W, b, Wout, bout, Wout1, bout1
    const void*  ei   = d_in[1];
    const float* ef   = (const float*)d_in[2];
    const float* ev   = (const float*)d_in[3];
    const float* W1   = (const float*)d_in[4];
    const float* b1   = (const float*)d_in[5];
    const float* W2   = (const float*)d_in[6];
    const float* b2   = (const float*)d_in[7];
    const float* W    = (const float*)d_in[8];
    const float* b    = (const float*)d_in[9];
    const float* Wout = (const float*)d_in[10];
    const float* bout = (const float*)d_in[11];
    const float* Wout1= (const float*)d_in[12];
    const float* bout1= (const float*)d_in[13];
    float* out = (float*)d_out;

    probe_idx_kernel<<<1, 1>>>((const int*)ei);
    setup_kernel<<<1, 256>>>(W2, b2, W, b);
    t4_kernel<<<(M_NODES + 255) / 256, 256>>>(ev, W1, b1);
    edge_kernel<<<(NE_HALF + 127) / 128, 128>>>(ei, ef, W2, b2);
    out_kernel<<<(M_NODES + 255) / 256, 256>>>(out, Wout, bout, Wout1, bout1);
}

// round 10
// speedup vs baseline: 1.2875x; 1.2875x over previous
#include <cuda_runtime.h>
#include <cstdint>

#define M_NODES 150000      // 3 * NATOMS
#define NE_EDGES 1500000
#define NE_HALF  750000
#define NHEADS 4
#define DHEAD 16

typedef unsigned long long ull;

// Device-global scratch
__device__ float  g_t4[M_NODES * 4];       // per-node low-rank features
__device__ float  g_UZ[M_NODES * 20];      // [4 heads x 4 U] + [4 Z]
__device__ float  g_A[256];                // A[d*4+i] = (W2@W)[i,d]
__device__ float  g_c[64];                 // c[d] = (b2@W + b)[d]
// packed-by-d-pair tables (dp = d/2, 32 pairs)
__device__ float2 g_Wp[32 * 16];           // Wp[dp*16+k] = (W[k,2dp], W[k,2dp+1])
__device__ float2 g_ABC[32 * 6];           // per dp: {A0,A1,A2,A3,b,c} pairs (48B record)
__device__ int    g_idx_is_64;

__device__ __forceinline__ float elu1(float v) {
    return v > 0.0f ? v : (__expf(v) - 1.0f);
}

__device__ __forceinline__ void red_add_v4(float* addr, float4 v) {
    asm volatile("red.global.add.v4.f32 [%0], {%1, %2, %3, %4};"
                 :: "l"(addr), "f"(v.x), "f"(v.y), "f"(v.z), "f"(v.w)
                 : "memory");
}

// packed f32x2 helpers (Blackwell): FFMA2 via PTX only
__device__ __forceinline__ ull pk2(float lo, float hi) {
    ull r; asm("mov.b64 %0, {%1, %2};" : "=l"(r) : "f"(lo), "f"(hi)); return r;
}
__device__ __forceinline__ void upk2(float& lo, float& hi, ull v) {
    asm("mov.b64 {%0, %1}, %2;" : "=f"(lo), "=f"(hi) : "l"(v));
}
__device__ __forceinline__ void fma2(ull& d, ull a, ull b) {   // d = a*b + d
    asm("fma.rn.f32x2 %0, %1, %2, %0;" : "+l"(d) : "l"(a), "l"(b));
}
__device__ __forceinline__ ull mul2(ull a, ull b) {
    ull r; asm("mul.rn.f32x2 %0, %1, %2;" : "=l"(r) : "l"(a), "l"(b)); return r;
}

// ---------------------------------------------------------------------------
__global__ void probe_idx_kernel(const int* __restrict__ ei32) {
    int z = (ei32[1] == 0) & (ei32[3] == 0) & (ei32[5] == 0) & (ei32[7] == 0);
    g_idx_is_64 = z;
}

// ---------------------------------------------------------------------------
// Setup: A = W2@W, c = b2@W + b, plus d-pair-packed tables. One block of 256.
// ---------------------------------------------------------------------------
__global__ void setup_kernel(const float* __restrict__ W2, const float* __restrict__ b2,
                             const float* __restrict__ W,  const float* __restrict__ b) {
    __shared__ float shA[256], shc[64];
    int t = threadIdx.x;           // t = d*4 + i
    int d = t >> 2, i = t & 3;
    float a = 0.f;
#pragma unroll
    for (int k = 0; k < 16; k++) a = fmaf(W2[i * 16 + k], W[k * 64 + d], a);
    shA[t] = a;
    if (i == 0) {
        float cc = b[d];
#pragma unroll
        for (int k = 0; k < 16; k++) cc = fmaf(b2[k], W[k * 64 + d], cc);
        shc[d] = cc;
    }
    __syncthreads();

    g_A[t] = shA[t];
    if (t < 64) g_c[t] = shc[t];

    if (t < 32) {                  // dp = t
        int dp = t;
#pragma unroll
        for (int k = 0; k < 16; k++)
            g_Wp[dp * 16 + k] = make_float2(W[k * 64 + 2 * dp], W[k * 64 + 2 * dp + 1]);
        // merged record: A0..A3, b, c (each a (d,d+1) pair)
#pragma unroll
        for (int i2 = 0; i2 < 4; i2++)
            g_ABC[dp * 6 + i2] = make_float2(shA[(2 * dp) * 4 + i2], shA[(2 * dp + 1) * 4 + i2]);
        g_ABC[dp * 6 + 4] = make_float2(b[2 * dp], b[2 * dp + 1]);
        g_ABC[dp * 6 + 5] = make_float2(shc[2 * dp], shc[2 * dp + 1]);
    }
}

// ---------------------------------------------------------------------------
// Kernel A: t4[m] = elu(x*W1 + b1); zero the UZ accumulator row.
// ---------------------------------------------------------------------------
__global__ __launch_bounds__(256)
void t4_kernel(const float* __restrict__ ev,
               const float* __restrict__ W1, const float* __restrict__ b1) {
    __shared__ float sW1[4], sb1[4];
    int t = threadIdx.x;
    if (t < 4) { sW1[t] = W1[t]; sb1[t] = b1[t]; }
    __syncthreads();

    int m = blockIdx.x * blockDim.x + t;
    if (m >= M_NODES) return;

    float x = ev[m];
    float4 t4;
    t4.x = elu1(fmaf(x, sW1[0], sb1[0]));
    t4.y = elu1(fmaf(x, sW1[1], sb1[1]));
    t4.z = elu1(fmaf(x, sW1[2], sb1[2]));
    t4.w = elu1(fmaf(x, sW1[3], sb1[3]));
    reinterpret_cast<float4*>(g_t4)[m] = t4;

    float4 z4 = make_float4(0.f, 0.f, 0.f, 0.f);
    float4* uz = reinterpret_cast<float4*>(g_UZ + (size_t)m * 20);
#pragma unroll
    for (int k = 0; k < 5; k++) uz[k] = z4;
}

// ---------------------------------------------------------------------------
// Kernel B: TWO edges per thread (e and e+NE/2), d-pair f32x2 lanes.
// Weight loads amortized over 2 d's AND 2 edges. A/b/c merged to 3 LDS.128.
// ---------------------------------------------------------------------------
__global__ __launch_bounds__(128, 4)
void edge_kernel(const void* __restrict__ ei_raw,
                 const float* __restrict__ ef,
                 const float* __restrict__ W2, const float* __restrict__ b2) {
    __shared__ ull  sWp[512];          // [dp][k] packed pairs (4 KB)
    __shared__ ull  sABC[192];         // [dp][{A0,A1,A2,A3,b,c}] (1.5 KB)
    __shared__ float sW2[64], sb2[16];

    int t = threadIdx.x;
    {
        const ull* wp = (const ull*)g_Wp;
#pragma unroll
        for (int i = 0; i < 4; i++) sWp[t + 128 * i] = wp[t + 128 * i];
        const ull* abc = (const ull*)g_ABC;
        sABC[t] = abc[t];                       // 0..127
        if (t < 64) sABC[t + 128] = abc[t + 128];   // 128..191
        if (t < 64)  sW2[t] = W2[t];
        if (t < 16)  sb2[t] = b2[t];
    }
    __syncthreads();

    int ea = blockIdx.x * blockDim.x + t;
    if (ea >= NE_HALF) return;
    int eb = ea + NE_HALF;

    int srcA, dstA, srcB, dstB;
    if (g_idx_is_64) {
        const long long* ei = (const long long*)ei_raw;
        srcA = (int)__ldg(ei + ea);
        dstA = (int)__ldg(ei + NE_EDGES + ea);
        srcB = (int)__ldg(ei + eb);
        dstB = (int)__ldg(ei + NE_EDGES + eb);
    } else {
        const int* ei = (const int*)ei_raw;
        srcA = __ldg(ei + ea);
        dstA = __ldg(ei + NE_EDGES + ea);
        srcB = __ldg(ei + eb);
        dstB = __ldg(ei + NE_EDGES + eb);
    }

    // front-batch all gathers (MLP)
    float4 tsvA = __ldg(reinterpret_cast<const float4*>(g_t4) + srcA);
    float4 tqvA = __ldg(reinterpret_cast<const float4*>(g_t4) + dstA);
    float4 tsvB = __ldg(reinterpret_cast<const float4*>(g_t4) + srcB);
    float4 tqvB = __ldg(reinterpret_cast<const float4*>(g_t4) + dstB);
    float4 fA = __ldg(reinterpret_cast<const float4*>(ef) + ea);
    float4 fB = __ldg(reinterpret_cast<const float4*>(ef) + eb);

    float efA[4] = {fA.x, fA.y, fA.z, fA.w};
    float efB[4] = {fB.x, fB.y, fB.z, fB.w};

    // e16 for both edges, sharing W2 reads; dup-packed pairs
    ull e2a[16], e2b[16];
#pragma unroll
    for (int k = 0; k < 16; k++) {
        float w0 = sW2[0 * 16 + k], w1 = sW2[1 * 16 + k];
        float w2 = sW2[2 * 16 + k], w3 = sW2[3 * 16 + k];
        float bb = sb2[k];
        float va = bb, vb = bb;
        va = fmaf(efA[0], w0, va); vb = fmaf(efB[0], w0, vb);
        va = fmaf(efA[1], w1, va); vb = fmaf(efB[1], w1, vb);
        va = fmaf(efA[2], w2, va); vb = fmaf(efB[2], w2, vb);
        va = fmaf(efA[3], w3, va); vb = fmaf(efB[3], w3, vb);
        va = elu1(va); vb = elu1(vb);
        e2a[k] = pk2(va, va);
        e2b[k] = pk2(vb, vb);
    }

    ull tq2a[4] = {pk2(tqvA.x, tqvA.x), pk2(tqvA.y, tqvA.y),
                   pk2(tqvA.z, tqvA.z), pk2(tqvA.w, tqvA.w)};
    ull tq2b[4] = {pk2(tqvB.x, tqvB.x), pk2(tqvB.y, tqvB.y),
                   pk2(tqvB.z, tqvB.z), pk2(tqvB.w, tqvB.w)};
    float tsA[4] = {tsvA.x, tsvA.y, tsvA.z, tsvA.w};
    float tsB[4] = {tsvB.x, tsvB.y, tsvB.z, tsvB.w};

    float* uzA = g_UZ + (size_t)dstA * 20;
    float* uzB = g_UZ + (size_t)dstB * 20;
    float zaccA[NHEADS], zaccB[NHEADS];

#pragma unroll
    for (int h = 0; h < NHEADS; h++) {
        ull VA0 = 0, VA1 = 0, VA2 = 0, VA3 = 0, VAc = 0;
        ull VB0 = 0, VB1 = 0, VB2 = 0, VB3 = 0, VBc = 0;
#pragma unroll
        for (int dpo = 0; dpo < 8; dpo++) {
            int dp = h * 8 + dpo;
            // merged A/b/c record: 3 x LDS.128
            const ulonglong2* abc = reinterpret_cast<const ulonglong2*>(sABC + dp * 6);
            ulonglong2 x0 = abc[0];    // A0, A1
            ulonglong2 x1 = abc[1];    // A2, A3
            ulonglong2 x2 = abc[2];    // b,  c
            ull a0 = x0.x, a1 = x0.y, a2 = x1.x, a3 = x1.y;
            ull bU = x2.x, cU = x2.y;

            ull E2a = bU, E2b = bU;
            const ulonglong2* wp2 = reinterpret_cast<const ulonglong2*>(sWp) + dp * 8;
#pragma unroll
            for (int kk = 0; kk < 8; kk++) {
                ulonglong2 ww = wp2[kk];
                fma2(E2a, e2a[2 * kk],     ww.x);
                fma2(E2b, e2b[2 * kk],     ww.x);
                fma2(E2a, e2a[2 * kk + 1], ww.y);
                fma2(E2b, e2b[2 * kk + 1], ww.y);
            }

            ull Q2a = cU, Q2b = cU;
            fma2(Q2a, tq2a[0], a0); fma2(Q2b, tq2b[0], a0);
            fma2(Q2a, tq2a[1], a1); fma2(Q2b, tq2b[1], a1);
            fma2(Q2a, tq2a[2], a2); fma2(Q2b, tq2b[2], a2);
            fma2(Q2a, tq2a[3], a3); fma2(Q2b, tq2b[3], a3);

            ull R2a = mul2(E2a, Q2a);
            ull R2b = mul2(E2b, Q2b);

            fma2(VA0, R2a, a0); fma2(VB0, R2b, a0);
            fma2(VA1, R2a, a1); fma2(VB1, R2b, a1);
            fma2(VA2, R2a, a2); fma2(VB2, R2b, a2);
            fma2(VA3, R2a, a3); fma2(VB3, R2b, a3);
            fma2(VAc, R2a, cU); fma2(VBc, R2b, cU);
        }
        // reduce packed accumulators — edge A
        {
            float l, hi, v0, v1, v2, v3, vc;
            upk2(l, hi, VA0); v0 = l + hi;
            upk2(l, hi, VA1); v1 = l + hi;
            upk2(l, hi, VA2); v2 = l + hi;
            upk2(l, hi, VA3); v3 = l + hi;
            upk2(l, hi, VAc); vc = l + hi;
            float sc = vc;
            sc = fmaf(tsA[0], v0, sc); sc = fmaf(tsA[1], v1, sc);
            sc = fmaf(tsA[2], v2, sc); sc = fmaf(tsA[3], v3, sc);
            sc *= 0.25f;
            sc = fminf(fmaxf(sc, -5.0f), 5.0f);
            float w = __expf(sc);
            zaccA[h] = w;
            red_add_v4(uzA + h * 4,
                       make_float4(tsA[0] * w, tsA[1] * w, tsA[2] * w, tsA[3] * w));
        }
        // edge B
        {
            float l, hi, v0, v1, v2, v3, vc;
            upk2(l, hi, VB0); v0 = l + hi;
            upk2(l, hi, VB1); v1 = l + hi;
            upk2(l, hi, VB2); v2 = l + hi;
            upk2(l, hi, VB3); v3 = l + hi;
            upk2(l, hi, VBc); vc = l + hi;
            float sc = vc;
            sc = fmaf(tsB[0], v0, sc); sc = fmaf(tsB[1], v1, sc);
            sc = fmaf(tsB[2], v2, sc); sc = fmaf(tsB[3], v3, sc);
            sc *= 0.25f;
            sc = fminf(fmaxf(sc, -5.0f), 5.0f);
            float w = __expf(sc);
            zaccB[h] = w;
            red_add_v4(uzB + h * 4,
                       make_float4(tsB[0] * w, tsB[1] * w, tsB[2] * w, tsB[3] * w));
        }
    }
    red_add_v4(uzA + 16, make_float4(zaccA[0], zaccA[1], zaccA[2], zaccA[3]));
    red_add_v4(uzB + 16, make_float4(zaccB[0], zaccB[1], zaccB[2], zaccB[3]));
}

// ---------------------------------------------------------------------------
// Kernel C: wV_d = A[:,d].U_h + c_d*Z_h ; h_d = wV_d/(Z_h+1e-6);
//           out = elu(h @ Wout + bout) @ Wout1 + bout1
// ---------------------------------------------------------------------------
__global__ __launch_bounds__(256)
void out_kernel(float* __restrict__ out,
                const float* __restrict__ Wout,  const float* __restrict__ bout,
                const float* __restrict__ Wout1, const float* __restrict__ bout1) {
    __shared__ float sWo[1024], sbo[16], sW1[16], sb1, sA[256], sc_[64];
    int t = threadIdx.x;
    for (int i = t; i < 1024; i += blockDim.x) sWo[i] = Wout[i];
    if (t < 16) { sbo[t] = bout[t]; sW1[t] = Wout1[t]; }
    if (t == 0) sb1 = bout1[0];
    if (t < 256) sA[t] = g_A[t];
    if (t < 64)  sc_[t] = g_c[t];
    __syncthreads();

    int m = blockIdx.x * blockDim.x + t;
    if (m >= M_NODES) return;

    const float4* uz4 = reinterpret_cast<const float4*>(g_UZ + (size_t)m * 20);
    float4 U0 = uz4[0], U1 = uz4[1], U2 = uz4[2], U3 = uz4[3], Zv = uz4[4];
    float U[NHEADS][4] = {
        {U0.x, U0.y, U0.z, U0.w}, {U1.x, U1.y, U1.z, U1.w},
        {U2.x, U2.y, U2.z, U2.w}, {U3.x, U3.y, U3.z, U3.w}};
    float Z[NHEADS] = {Zv.x, Zv.y, Zv.z, Zv.w};

    float acc[16];
#pragma unroll
    for (int k = 0; k < 16; k++) acc[k] = sbo[k];

#pragma unroll
    for (int h = 0; h < NHEADS; h++) {
        float rz = 1.0f / (Z[h] + 1e-6f);
#pragma unroll
        for (int dd = 0; dd < 16; dd++) {
            int d = h * 16 + dd;
            float wv = sc_[d] * Z[h];
#pragma unroll
            for (int i = 0; i < 4; i++) wv = fmaf(sA[d * 4 + i], U[h][i], wv);
            float hv = wv * rz;
#pragma unroll
            for (int k = 0; k < 16; k++) acc[k] = fmaf(hv, sWo[d * 16 + k], acc[k]);
        }
    }

    float val = sb1;
#pragma unroll
    for (int k = 0; k < 16; k++) {
        float a = elu1(acc[k]);
        val = fmaf(a, sW1[k], val);
    }
    out[m] = val;
}

// ---------------------------------------------------------------------------
extern "C" void kernel_launch(void* const* d_in, const int* in_sizes, int n_in,
                              void* d_out, int out_size) {
    // order: node_attr, edge_index, edge_feature, edge_vector,
    //        W1, b1, W2, b2, W, b, Wout, bout, Wout1, bout1
    const void*  ei   = d_in[1];
    const float* ef   = (const float*)d_in[2];
    const float* ev   = (const float*)d_in[3];
    const float* W1   = (const float*)d_in[4];
    const float* b1   = (const float*)d_in[5];
    const float* W2   = (const float*)d_in[6];
    const float* b2   = (const float*)d_in[7];
    const float* W    = (const float*)d_in[8];
    const float* b    = (const float*)d_in[9];
    const float* Wout = (const float*)d_in[10];
    const float* bout = (const float*)d_in[11];
    const float* Wout1= (const float*)d_in[12];
    const float* bout1= (const float*)d_in[13];
    float* out = (float*)d_out;

    probe_idx_kernel<<<1, 1>>>((const int*)ei);
    setup_kernel<<<1, 256>>>(W2, b2, W, b);
    t4_kernel<<<(M_NODES + 255) / 256, 256>>>(ev, W1, b1);
    edge_kernel<<<(NE_HALF + 127) / 128, 128>>>(ei, ef, W2, b2);
    out_kernel<<<(M_NODES + 255) / 256, 256>>>(out, Wout, bout, Wout1, bout1);
}